// round 12
// baseline (speedup 1.0000x reference)
#include <cuda_runtime.h>
#include <cstdint>

// embedding_bag(mode='mean'): B bags over a [V,64] fp32 table.  FINAL.
//
// Shape (empirically optimal over 11 tuning rounds on GB300/sm_103a):
//   - One HALF-WARP per bag; sublane s (0..15) owns one float4 (cols 4s..4s+3).
//     16 lanes x 16B = one full 256B row per half-warp; each warp LDG.E.128
//     covers TWO rows (512B per instruction).
//   - Unroll x4 (2KB in flight per warp) + 2-wide tail so L=50 (12*4+2)
//     never enters a serialized scalar loop.
//   - 256-thread CTAs, 32 regs, 8 CTAs/SM (__launch_bounds__ enforced).
//   - Row addresses are u32 BYTE offsets (V*256B = 256MB fits u32).
//
// Cache policy (intrinsics only — asm volatile in the hot loop blocks ptxas
// from front-batching the index loads, measured +2.1us):
//   - weight gathers: __ldcg (L2-only; L1 hit rate ~0% on a 143MB random
//     footprint, so L1 fills are pure overhead)
//   - output: __stcs (write-once streaming)
//   - indices/offsets: __ldg (small, read-once, front-batched by ptxas)
//
// Measured (replicated): 31.2-31.5us wall, 5.20 TB/s HBM (66% busy) — at the
// random-256B-granule DRAM efficiency ceiling; DRAM traffic equals the
// compulsory unique-row footprint plus bounded L2 capacity misses.

__global__ __launch_bounds__(256, 8)
void embag_mean_kernel(const void* __restrict__ indices_raw,
                       const void* __restrict__ offsets_raw,
                       const char* __restrict__ weight_bytes,
                       float* __restrict__ out,
                       int num_bags, long long total_indices) {
    const int warp_global = (int)((blockIdx.x * (unsigned)blockDim.x + threadIdx.x) >> 5);
    const int lane = threadIdx.x & 31;
    const int half = lane >> 4;        // bag within the warp
    const int sub  = lane & 15;        // float4 column group within the row
    const int bag  = 2 * warp_global + half;
    if (bag >= num_bags) return;

    const char* __restrict__ wbase = weight_bytes + (unsigned)(sub * 16);

    // Inline dtype detection (int64 vs int32 indices): ids < 2^31, so an
    // int64 LE buffer has every odd 32-bit word zero; an int32 buffer has
    // random nonzero ids there (P[all 4 zero] ~ 1e-24). Uniform result.
    const int* wprobe = (const int*)indices_raw;
    int allz = 1;
    #pragma unroll
    for (int k = 1; k < 9; k += 2) allz &= (__ldg(&wprobe[k]) == 0);
    const bool is64 = (allz != 0);

    const long long* __restrict__ idx64 = (const long long*)indices_raw;
    const int*       __restrict__ idx32 = (const int*)indices_raw;
    const long long* __restrict__ off64 = (const long long*)offsets_raw;
    const int*       __restrict__ off32 = (const int*)offsets_raw;

    long long start, end;
    if (is64) {
        start = __ldg(&off64[bag]);
        end   = (bag + 1 < num_bags) ? __ldg(&off64[bag + 1]) : total_indices;
    } else {
        start = (long long)__ldg(&off32[bag]);
        end   = (bag + 1 < num_bags) ? (long long)__ldg(&off32[bag + 1]) : total_indices;
    }

    float4 acc = make_float4(0.f, 0.f, 0.f, 0.f);

    long long i = start;
    // Main loop: 4 independent 512B row-pair gathers in flight per warp.
    #pragma unroll 1
    for (; i + 4 <= end; i += 4) {
        unsigned o0, o1, o2, o3;
        if (is64) {
            o0 = (unsigned)__ldg(&idx64[i    ]) << 8;
            o1 = (unsigned)__ldg(&idx64[i + 1]) << 8;
            o2 = (unsigned)__ldg(&idx64[i + 2]) << 8;
            o3 = (unsigned)__ldg(&idx64[i + 3]) << 8;
        } else {
            o0 = (unsigned)__ldg(&idx32[i    ]) << 8;
            o1 = (unsigned)__ldg(&idx32[i + 1]) << 8;
            o2 = (unsigned)__ldg(&idx32[i + 2]) << 8;
            o3 = (unsigned)__ldg(&idx32[i + 3]) << 8;
        }
        float4 v0 = __ldcg((const float4*)(wbase + o0));
        float4 v1 = __ldcg((const float4*)(wbase + o1));
        float4 v2 = __ldcg((const float4*)(wbase + o2));
        float4 v3 = __ldcg((const float4*)(wbase + o3));
        acc.x += (v0.x + v1.x) + (v2.x + v3.x);
        acc.y += (v0.y + v1.y) + (v2.y + v3.y);
        acc.z += (v0.z + v1.z) + (v2.z + v3.z);
        acc.w += (v0.w + v1.w) + (v2.w + v3.w);
    }
    // 2-wide tail (covers L % 4 == 2/3 without full serialization).
    if (i + 2 <= end) {
        unsigned o0, o1;
        if (is64) {
            o0 = (unsigned)__ldg(&idx64[i    ]) << 8;
            o1 = (unsigned)__ldg(&idx64[i + 1]) << 8;
        } else {
            o0 = (unsigned)__ldg(&idx32[i    ]) << 8;
            o1 = (unsigned)__ldg(&idx32[i + 1]) << 8;
        }
        float4 v0 = __ldcg((const float4*)(wbase + o0));
        float4 v1 = __ldcg((const float4*)(wbase + o1));
        acc.x += v0.x + v1.x;
        acc.y += v0.y + v1.y;
        acc.z += v0.z + v1.z;
        acc.w += v0.w + v1.w;
        i += 2;
    }
    if (i < end) {
        unsigned o = (is64 ? (unsigned)__ldg(&idx64[i])
                           : (unsigned)__ldg(&idx32[i])) << 8;
        float4 v = __ldcg((const float4*)(wbase + o));
        acc.x += v.x; acc.y += v.y; acc.z += v.z; acc.w += v.w;
    }

    const long long cnt = end - start;
    const float inv = 1.0f / (float)(cnt > 0 ? cnt : 1);
    acc.x *= inv; acc.y *= inv; acc.z *= inv; acc.w *= inv;

    __stcs(((float4*)out) + (size_t)bag * 16 + sub, acc);
}

extern "C" void kernel_launch(void* const* d_in, const int* in_sizes, int n_in,
                              void* d_out, int out_size) {
    // metadata order: indices [T], offsets [B], weight [V*D]
    const void* indices = d_in[0];
    const void* offsets = d_in[1];
    const char* weight  = (const char*)d_in[2];
    float*      out     = (float*)d_out;

    const int       num_bags      = in_sizes[1];
    const long long total_indices = in_sizes[0];

    // 2 bags per warp, 8 warps per block -> 16 bags per block.
    const int bags_per_block = 16;
    const int blocks = (num_bags + bags_per_block - 1) / bags_per_block;
    embag_mean_kernel<<<blocks, 256>>>(indices, offsets, weight, out,
                                       num_bags, total_indices);
}

// round 13
// speedup vs baseline: 1.0092x; 1.0092x over previous
#include <cuda_runtime.h>
#include <cstdint>

// embedding_bag(mode='mean'): B bags over a [V,64] fp32 table.
//
// Shape (empirically optimal over 12 tuning rounds on GB300/sm_103a):
//   - One HALF-WARP per bag; sublane s (0..15) owns one float4 (cols 4s..4s+3).
//     16 lanes x 16B = one full 256B row per half-warp; each warp LDG.E.128
//     covers TWO rows (512B per instruction).
//   - Unroll x4 (2KB in flight per warp) + 2-wide tail (L=50 = 12*4+2).
//   - 256-thread CTAs, 32 regs, 8 CTAs/SM.
//   - NEW: persistent grid of exactly 148*8 = 1184 CTAs (one full wave, 8 on
//     EVERY SM) with warp-level grid-stride over bag pairs — removes the
//     7-vs-6 CTA/SM placement imbalance of the 1024-CTA launch.
//   - Row addresses are u32 BYTE offsets (V*256B = 256MB fits u32).
//
// Cache policy (intrinsics only — asm volatile in the hot loop blocks ptxas
// index-load batching, measured +2.1us):
//   - weight gathers: __ldcg (L2-only; L1 hit ~0% on a 143MB random footprint)
//   - output: __stcs (write-once streaming)
//   - indices/offsets: __ldg

#define NUM_SMS 148
#define CTAS_PER_SM 8

template <typename IDX>
static __device__ __forceinline__ void process_bag(
    const IDX* __restrict__ idx,
    const char* __restrict__ wbase,
    float* __restrict__ out,
    int sub, int bag,
    long long start, long long end)
{
    float4 acc = make_float4(0.f, 0.f, 0.f, 0.f);

    long long i = start;
    #pragma unroll 1
    for (; i + 4 <= end; i += 4) {
        unsigned o0 = (unsigned)__ldg(&idx[i    ]) << 8;
        unsigned o1 = (unsigned)__ldg(&idx[i + 1]) << 8;
        unsigned o2 = (unsigned)__ldg(&idx[i + 2]) << 8;
        unsigned o3 = (unsigned)__ldg(&idx[i + 3]) << 8;
        float4 v0 = __ldcg((const float4*)(wbase + o0));
        float4 v1 = __ldcg((const float4*)(wbase + o1));
        float4 v2 = __ldcg((const float4*)(wbase + o2));
        float4 v3 = __ldcg((const float4*)(wbase + o3));
        acc.x += (v0.x + v1.x) + (v2.x + v3.x);
        acc.y += (v0.y + v1.y) + (v2.y + v3.y);
        acc.z += (v0.z + v1.z) + (v2.z + v3.z);
        acc.w += (v0.w + v1.w) + (v2.w + v3.w);
    }
    if (i + 2 <= end) {
        unsigned o0 = (unsigned)__ldg(&idx[i    ]) << 8;
        unsigned o1 = (unsigned)__ldg(&idx[i + 1]) << 8;
        float4 v0 = __ldcg((const float4*)(wbase + o0));
        float4 v1 = __ldcg((const float4*)(wbase + o1));
        acc.x += v0.x + v1.x;
        acc.y += v0.y + v1.y;
        acc.z += v0.z + v1.z;
        acc.w += v0.w + v1.w;
        i += 2;
    }
    if (i < end) {
        unsigned o = (unsigned)__ldg(&idx[i]) << 8;
        float4 v = __ldcg((const float4*)(wbase + o));
        acc.x += v.x; acc.y += v.y; acc.z += v.z; acc.w += v.w;
    }

    const long long cnt = end - start;
    const float inv = 1.0f / (float)(cnt > 0 ? cnt : 1);
    acc.x *= inv; acc.y *= inv; acc.z *= inv; acc.w *= inv;

    __stcs(((float4*)out) + (size_t)bag * 16 + sub, acc);
}

template <typename IDX>
static __device__ __forceinline__ void run_all(
    const IDX* __restrict__ idx,
    const IDX* __restrict__ off,
    const char* __restrict__ weight_bytes,
    float* __restrict__ out,
    int num_bags, long long total_indices,
    int warp_global, int total_warps, int half, int sub)
{
    const char* __restrict__ wbase = weight_bytes + (unsigned)(sub * 16);
    // Grid-stride over bag pairs: warp w handles bags {2w+half} then strides.
    for (int bag = 2 * warp_global + half; bag < num_bags; bag += 2 * total_warps) {
        long long start = (long long)__ldg(&off[bag]);
        long long end   = (bag + 1 < num_bags) ? (long long)__ldg(&off[bag + 1])
                                               : total_indices;
        process_bag<IDX>(idx, wbase, out, sub, bag, start, end);
    }
}

__global__ __launch_bounds__(256, 8)
void embag_mean_kernel(const void* __restrict__ indices_raw,
                       const void* __restrict__ offsets_raw,
                       const char* __restrict__ weight_bytes,
                       float* __restrict__ out,
                       int num_bags, long long total_indices) {
    const int warp_global = (int)((blockIdx.x * (unsigned)blockDim.x + threadIdx.x) >> 5);
    const int total_warps = (int)((gridDim.x * (unsigned)blockDim.x) >> 5);
    const int lane = threadIdx.x & 31;
    const int half = lane >> 4;        // bag within the warp
    const int sub  = lane & 15;        // float4 column group within the row

    // Inline dtype detection (int64 vs int32 indices): ids < 2^31, so an
    // int64 LE buffer has every odd 32-bit word zero; an int32 buffer has
    // random nonzero ids there (P[all 4 zero] ~ 1e-24). Uniform result.
    const int* wprobe = (const int*)indices_raw;
    int allz = 1;
    #pragma unroll
    for (int k = 1; k < 9; k += 2) allz &= (__ldg(&wprobe[k]) == 0);

    if (allz) {
        run_all<long long>((const long long*)indices_raw,
                           (const long long*)offsets_raw,
                           weight_bytes, out, num_bags, total_indices,
                           warp_global, total_warps, half, sub);
    } else {
        run_all<int>((const int*)indices_raw,
                     (const int*)offsets_raw,
                     weight_bytes, out, num_bags, total_indices,
                     warp_global, total_warps, half, sub);
    }
}

extern "C" void kernel_launch(void* const* d_in, const int* in_sizes, int n_in,
                              void* d_out, int out_size) {
    // metadata order: indices [T], offsets [B], weight [V*D]
    const void* indices = d_in[0];
    const void* offsets = d_in[1];
    const char* weight  = (const char*)d_in[2];
    float*      out     = (float*)d_out;

    const int       num_bags      = in_sizes[1];
    const long long total_indices = in_sizes[0];

    // One full, perfectly balanced wave: 8 CTAs on every SM.
    int blocks = NUM_SMS * CTAS_PER_SM;   // 1184
    const int max_useful = (num_bags + 15) / 16;  // 16 bags per CTA minimum
    if (blocks > max_useful) blocks = max_useful;

    embag_mean_kernel<<<blocks, 256>>>(indices, offsets, weight, out,
                                       num_bags, total_indices);
}